// round 16
// baseline (speedup 1.0000x reference)
#include <cuda_runtime.h>
#include <cuda_fp16.h>
#include <cstdint>
#include <math.h>

// Problem constants
#define M_ROWS   4096      // B*S
#define NTDIM    1024
#define NGROUP   64        // B*heads
#define DPH      64
#define SEQ      1024
#define LNEPS    1e-5f
// softmax scale folded into Q:  q' = q * log2(e)/32;  E = 2^relu(q'.k)
#define QSCALE   0.04508422002777998f

// Scratch (allocation-free rule: __device__ globals), all fp16
__device__ __half g_q[M_ROWS * NTDIM];
__device__ __half g_k[M_ROWS * NTDIM];
__device__ __half g_v[M_ROWS * NTDIM];
__device__ __half g_ctx[M_ROWS * NTDIM];
__device__ __half g_x[M_ROWS * NTDIM];
__device__ __half g_w[3 * NTDIM * NTDIM];

// ===========================================================================
// PTX helpers: mma.sync (HMMA f16) + ldmatrix + cp.async
// ===========================================================================
__device__ __forceinline__ uint32_t smem_u32(const void* p) {
    uint32_t a;
    asm("{ .reg .u64 t; cvta.to.shared.u64 t, %1; cvt.u32.u64 %0, t; }" : "=r"(a) : "l"(p));
    return a;
}
__device__ __forceinline__ void ldsm_x4(uint32_t* r, uint32_t addr) {
    asm volatile("ldmatrix.sync.aligned.m8n8.x4.shared.b16 {%0,%1,%2,%3}, [%4];"
                 : "=r"(r[0]), "=r"(r[1]), "=r"(r[2]), "=r"(r[3]) : "r"(addr));
}
__device__ __forceinline__ void ldsm_x4_t(uint32_t* r, uint32_t addr) {
    asm volatile("ldmatrix.sync.aligned.m8n8.x4.trans.shared.b16 {%0,%1,%2,%3}, [%4];"
                 : "=r"(r[0]), "=r"(r[1]), "=r"(r[2]), "=r"(r[3]) : "r"(addr));
}
__device__ __forceinline__ void mma_f16(float* d, const uint32_t* a,
                                        uint32_t b0, uint32_t b1) {
    asm volatile(
        "mma.sync.aligned.m16n8k16.row.col.f32.f16.f16.f32 "
        "{%0,%1,%2,%3}, {%4,%5,%6,%7}, {%8,%9}, {%0,%1,%2,%3};"
        : "+f"(d[0]), "+f"(d[1]), "+f"(d[2]), "+f"(d[3])
        : "r"(a[0]), "r"(a[1]), "r"(a[2]), "r"(a[3]), "r"(b0), "r"(b1));
}
__device__ __forceinline__ void cpa16(uint32_t dst, const void* src) {
    size_t gp;
    asm("cvta.to.global.u64 %0, %1;" : "=l"(gp) : "l"(src));
    asm volatile("cp.async.cg.shared.global [%0], [%1], 16;" :: "r"(dst), "l"(gp) : "memory");
}
__device__ __forceinline__ void cpa_commit() {
    asm volatile("cp.async.commit_group;" ::: "memory");
}
__device__ __forceinline__ void cpa_wait0() {
    asm volatile("cp.async.wait_group 0;" ::: "memory");
}
__device__ __forceinline__ void cpa_wait1() {
    asm volatile("cp.async.wait_group 1;" ::: "memory");
}
__device__ __forceinline__ uint32_t pack_h2(float lo, float hi) {
    __half2 v = __floats2half2_rn(lo, hi);
    return *reinterpret_cast<uint32_t*>(&v);
}
// bare MUFU exp2 (relu'd input is in [0, ~8])
__device__ __forceinline__ float ex2(float x) {
    float r;
    asm("ex2.approx.f32 %0, %1;" : "=f"(r) : "f"(x));
    return r;
}

// ---------------------------------------------------------------------------
// Kernel 0: fp32 -> fp16 for x + Wq + Wk + Wv; blocks < 256 also zero sums.
// ---------------------------------------------------------------------------
__global__ __launch_bounds__(256) void cvt_all_kernel(
    const float* __restrict__ x, const float* __restrict__ wq,
    const float* __restrict__ wk, const float* __restrict__ wv,
    float* __restrict__ sums)
{
    const int b = blockIdx.x;
    const float* src; __half* dst;
    if (b < 4096)      { src = x  + (size_t)b * 1024;          dst = g_x + (size_t)b * 1024; }
    else if (b < 5120) { src = wq + (size_t)(b - 4096) * 1024; dst = g_w + (size_t)(b - 4096) * 1024; }
    else if (b < 6144) { src = wk + (size_t)(b - 5120) * 1024; dst = g_w + 1048576 + (size_t)(b - 5120) * 1024; }
    else               { src = wv + (size_t)(b - 6144) * 1024; dst = g_w + 2097152 + (size_t)(b - 6144) * 1024; }
    const int i = threadIdx.x * 4;
    float4 v = *reinterpret_cast<const float4*>(src + i);
    uint2 u;
    u.x = pack_h2(v.x, v.y);
    u.y = pack_h2(v.z, v.w);
    *reinterpret_cast<uint2*>(dst + i) = u;
    if (b < 256) sums[b * 256 + threadIdx.x] = 0.0f;
}

// ---------------------------------------------------------------------------
// Kernel 1: QKV projection via mma.sync f16, fp32 accum, 3-stage cp.async.
// C = X @ W^T + b -> fp16.  CTA tile 128x256, warp tile 64x64, k-stage 64.
// grid (4 ntile, 32 mtile, 3).  Q output is pre-scaled by QSCALE.
// Smem/stage: A 128x64x2 = 16KB + B 256x64x2 = 32KB -> 48KB; x3 = 144KB.
// ---------------------------------------------------------------------------
#define QST_AH 0
#define QST_BH 16384
#define QST_SZ 49152
#define QKV_SMEM (3 * QST_SZ)

__global__ __launch_bounds__(256) void qkv_mma_kernel(
    const float* __restrict__ bq, const float* __restrict__ bk, const float* __restrict__ bv)
{
    extern __shared__ char smc[];
    const uint32_t smb = smem_u32(smc);
    const int t = threadIdx.x;
    const int w = t >> 5;
    const int l = t & 31;
    const int z = blockIdx.z;
    const __half* __restrict__ Wh = g_w + (size_t)z * NTDIM * NTDIM;
    const float* bias = (z == 0) ? bq : (z == 1) ? bk : bv;
    __half* outh = (z == 0) ? g_q : (z == 1) ? g_k : g_v;
    const float osc = (z == 0) ? QSCALE : 1.0f;
    const int m0 = blockIdx.y * 128;
    const int n0 = blockIdx.x * 256;
    const int wm0 = (w & 1) * 64;    // 2 m-groups of 64
    const int wn0 = (w >> 1) * 64;   // 4 n-groups of 64

    const int sc = t & 7;
    const int sr0 = t >> 3;          // 0..31

    float acc[4][8][4];
    #pragma unroll
    for (int a = 0; a < 4; a++)
        #pragma unroll
        for (int b = 0; b < 8; b++)
            #pragma unroll
            for (int c = 0; c < 4; c++) acc[a][b][c] = 0.0f;

    // staging: A 128 rows (4 chunks/thread), B 256 rows (8 chunks/thread)
    auto issue_stage = [&](int s, int buf) {
        const int k0 = s * 64;
        const uint32_t sb = smb + buf * QST_SZ;
        #pragma unroll
        for (int i = 0; i < 4; i++) {
            const int r = sr0 + i * 32;
            const uint32_t doff = r * 128 + (((sc ^ (r & 7)) << 4));
            cpa16(sb + QST_AH + doff, g_x + (size_t)(m0 + r) * NTDIM + k0 + sc * 8);
        }
        #pragma unroll
        for (int i = 0; i < 8; i++) {
            const int r = sr0 + i * 32;
            const uint32_t doff = r * 128 + (((sc ^ (r & 7)) << 4));
            cpa16(sb + QST_BH + doff, Wh + (size_t)(n0 + r) * NTDIM + k0 + sc * 8);
        }
        cpa_commit();
    };

    issue_stage(0, 0);
    issue_stage(1, 1);

    for (int s = 0; s < 16; s++) {
        if (s == 15) cpa_wait0(); else cpa_wait1();
        __syncthreads();
        if (s < 14) issue_stage(s + 2, (s + 2) % 3);
        const uint32_t bb = smb + (s % 3) * QST_SZ;

        #pragma unroll
        for (int kt = 0; kt < 4; kt++) {
            const int chunk = kt * 2 + (l >> 4);
            uint32_t ah[4][4];
            #pragma unroll
            for (int mf = 0; mf < 4; mf++) {
                const int r = wm0 + mf * 16 + (l & 15);
                ldsm_x4(ah[mf], bb + QST_AH + r * 128 + (((chunk ^ (r & 7)) << 4)));
            }
            #pragma unroll
            for (int nq = 0; nq < 4; nq++) {
                const int rr = wn0 + nq * 16 + (l & 15);
                uint32_t bh[4];
                ldsm_x4(bh, bb + QST_BH + rr * 128 + (((chunk ^ (rr & 7)) << 4)));
                #pragma unroll
                for (int mf = 0; mf < 4; mf++) {
                    #pragma unroll
                    for (int nh = 0; nh < 2; nh++)
                        mma_f16(acc[mf][nq * 2 + nh], ah[mf], bh[nh], bh[2 + nh]);
                }
            }
        }
    }

    // epilogue: (acc + bias) * osc -> fp16
    const int lr = l >> 2;
    const int lc = (l & 3) * 2;
    #pragma unroll
    for (int mf = 0; mf < 4; mf++) {
        #pragma unroll
        for (int nf = 0; nf < 8; nf++) {
            const int col = n0 + wn0 + nf * 8 + lc;
            const int row = m0 + wm0 + mf * 16 + lr;
            const float* d = acc[mf][nf];
            *reinterpret_cast<uint32_t*>(outh + (size_t)row * NTDIM + col) =
                pack_h2((d[0] + bias[col]) * osc, (d[1] + bias[col + 1]) * osc);
            *reinterpret_cast<uint32_t*>(outh + (size_t)(row + 8) * NTDIM + col) =
                pack_h2((d[2] + bias[col]) * osc, (d[3] + bias[col + 1]) * osc);
        }
    }
}

// ---------------------------------------------------------------------------
// Kernel 2: attention, single fused pass, 512 threads (16 warps).
// CTA = 64 query rows x one head-group.  Warp = 16 rows x 32-key slice.
// E = 2^relu(q'.k) via bare ex2 (scale pre-folded into q').
// E stored thread-linear in smem; rowsum reduction deferred; ctx out fp16.
// ---------------------------------------------------------------------------
#define A_ESM   0           // 8 jb x 16KB = 131072 (thread-linear layout)
#define A_QH    131072      // 8192
#define A_KV    139264      // 2 x (K 16384 + V 16384) = 65536 (loop only)
#define A_RED   139264      // 4 x 17408 = 69632 (epilogue, reuses KV)
#define A_RS    208896      // 64 floats
#define A_SMEM  209152

__global__ __launch_bounds__(512) void attn_mma_kernel(float* __restrict__ sums)
{
    extern __shared__ char smc[];
    const uint32_t smb = smem_u32(smc);
    float* rs = reinterpret_cast<float*>(smc + A_RS);

    const int ib = blockIdx.x;   // 0..15 (64-row block)
    const int g  = blockIdx.y;   // 0..63
    const int t  = threadIdx.x;
    const int w  = t >> 5;
    const int l  = t & 31;
    const int wm = w & 3;        // 4 row groups of 16
    const int wn = w >> 2;       // 4 key-slice groups of 32

    const __half* __restrict__ qhp = g_q + (size_t)g * 65536 + ib * 4096;
    const __half* __restrict__ khp = g_k + (size_t)g * 65536;
    const __half* __restrict__ vhp = g_v + (size_t)g * 65536;

    if (t < 64) rs[t] = 0.0f;

    // stage Q: 512 chunk-tasks, 1 per thread
    {
        int row = t >> 3, ch = t & 7;
        cpa16(smb + A_QH + row * 128 + ((ch ^ (row & 7)) << 4), qhp + row * 64 + ch * 8);
    }
    auto stage_kv = [&](int jb, int buf) {
        const uint32_t dst = smb + A_KV + buf * 32768;
        #pragma unroll
        for (int i = 0; i < 2; i++) {
            int id = t + i * 512;
            int row = id >> 3, ch = id & 7;
            uint32_t doff = row * 128 + ((ch ^ (row & 7)) << 4);
            cpa16(dst + doff, khp + (size_t)(jb * 128 + row) * 64 + ch * 8);
            cpa16(dst + 16384 + doff, vhp + (size_t)(jb * 128 + row) * 64 + ch * 8);
        }
        cpa_commit();
    };
    stage_kv(0, 0);

    float ev[8][4];
    #pragma unroll
    for (int b = 0; b < 8; b++)
        #pragma unroll
        for (int c = 0; c < 4; c++) ev[b][c] = 0.0f;

    uint32_t qf[4][4];            // hoisted Q fragments (loaded at jb==0)
    float sAcc0 = 0.0f, sAcc1 = 0.0f;   // deferred rowsum partials
    char* const epp = smc + A_ESM + t * 16;  // thread-linear E base

    for (int jb = 0; jb < 8; jb++) {
        cpa_wait0();
        __syncthreads();
        if (jb < 7) stage_kv(jb + 1, (jb + 1) & 1);
        const uint32_t kb = smb + A_KV + (jb & 1) * 32768;
        const uint32_t vb = kb + 16384;

        if (jb == 0) {
            #pragma unroll
            for (int kc = 0; kc < 4; kc++) {
                const int chunk = kc * 2 + (l >> 4);
                const int r = wm * 16 + (l & 15);
                ldsm_x4(qf[kc], smb + A_QH + r * 128 + ((chunk ^ (r & 7)) << 4));
            }
        }

        // ---- QK^T: warp owns rows wm*16.., cols wn*32.. -------------------
        float acc[4][4];
        #pragma unroll
        for (int b = 0; b < 4; b++)
            #pragma unroll
            for (int c = 0; c < 4; c++) acc[b][c] = 0.0f;

        #pragma unroll
        for (int kc = 0; kc < 4; kc++) {
            const int chunk = kc * 2 + (l >> 4);
            #pragma unroll
            for (int nfp = 0; nfp < 2; nfp++) {
                const int rr = wn * 32 + nfp * 16 + (l & 15);
                uint32_t bh[4];
                ldsm_x4(bh, kb + rr * 128 + ((chunk ^ (rr & 7)) << 4));
                #pragma unroll
                for (int nh = 0; nh < 2; nh++)
                    mma_f16(acc[nfp * 2 + nh], qf[kc], bh[nh], bh[2 + nh]);
            }
        }

        // ---- E = 2^relu(z'); E -> smem (2 x STS.128); reg rowsums ---------
        uint32_t pk[4][2];
        #pragma unroll
        for (int nf = 0; nf < 4; nf++) {
            float* d = acc[nf];
            float e0 = ex2(fmaxf(d[0], 0.0f));
            float e1 = ex2(fmaxf(d[1], 0.0f));
            float e2 = ex2(fmaxf(d[2], 0.0f));
            float e3 = ex2(fmaxf(d[3], 0.0f));
            sAcc0 += e0 + e1;
            sAcc1 += e2 + e3;
            pk[nf][0] = pack_h2(e0, e1);
            pk[nf][1] = pack_h2(e2, e3);
        }
        {
            uint4 u0 = make_uint4(pk[0][0], pk[1][0], pk[2][0], pk[3][0]);
            uint4 u1 = make_uint4(pk[0][1], pk[1][1], pk[2][1], pk[3][1]);
            *reinterpret_cast<uint4*>(epp + (jb << 14)) = u0;
            *reinterpret_cast<uint4*>(epp + (jb << 14) + 8192) = u1;
        }

        // ---- EV += E @ V over this warp's 32-key slice (2 k16 chunks) -----
        #pragma unroll
        for (int c = 0; c < 2; c++) {
            const int krow = wn * 32 + c * 16 + (l & 7) + (((l >> 3) & 1) << 3);
            uint32_t A[4] = { pk[2 * c][0], pk[2 * c][1],
                              pk[2 * c + 1][0], pk[2 * c + 1][1] };
            #pragma unroll
            for (int nt = 0; nt < 4; nt++) {
                const int nch = nt * 2 + (l >> 4);
                uint32_t vh4[4];
                ldsm_x4_t(vh4, vb + krow * 128 + ((nch ^ (krow & 7)) << 4));
                mma_f16(ev[2 * nt], A, vh4[0], vh4[1]);
                mma_f16(ev[2 * nt + 1], A, vh4[2], vh4[3]);
            }
        }
    }

    // deferred rowsum reduction: one shuffle-pass + one atomic pair
    {
        sAcc0 += __shfl_xor_sync(0xffffffffu, sAcc0, 1);
        sAcc0 += __shfl_xor_sync(0xffffffffu, sAcc0, 2);
        sAcc1 += __shfl_xor_sync(0xffffffffu, sAcc1, 1);
        sAcc1 += __shfl_xor_sync(0xffffffffu, sAcc1, 2);
        const int rbase = wm * 16 + (l >> 2);
        if ((l & 3) == 0) {
            atomicAdd(&rs[rbase], sAcc0);
            atomicAdd(&rs[rbase + 8], sAcc1);
        }
    }
    __syncthreads();   // rowsums complete; E smem stable; KV buffers free

    if (t < 64) rs[t] = 1.0f / rs[t];

    // ---- cross-warp EV reduce: write partials (row stride 272B, per wn) ---
    {
        char* red = smc + A_RED + wn * 17408;
        const int row = wm * 16 + (l >> 2);
        #pragma unroll
        for (int nf = 0; nf < 8; nf++) {
            const int col = nf * 8 + 2 * (l & 3);
            *reinterpret_cast<float2*>(red + row * 272 + col * 4) =
                make_float2(ev[nf][0], ev[nf][1]);
            *reinterpret_cast<float2*>(red + (row + 8) * 272 + col * 4) =
                make_float2(ev[nf][2], ev[nf][3]);
        }
    }
    __syncthreads();

    // ---- reduce 4 partials, scale by rinv, write ctx (fp16) ---------------
    {
        const int r = t >> 3;               // 0..63
        const float ri = rs[r];
        __half* __restrict__ Ch = g_ctx + (size_t)g * 65536 + ib * 4096;
        #pragma unroll
        for (int it = 0; it < 2; it++) {
            const int col = ((t & 7) * 2 + it) * 4;   // 0..60
            float4 s = make_float4(0.f, 0.f, 0.f, 0.f);
            #pragma unroll
            for (int p = 0; p < 4; p++) {
                float4 v = *reinterpret_cast<const float4*>(
                    smc + A_RED + p * 17408 + r * 272 + col * 4);
                s.x += v.x; s.y += v.y; s.z += v.z; s.w += v.w;
            }
            uint2 u;
            u.x = pack_h2(s.x * ri, s.y * ri);
            u.y = pack_h2(s.z * ri, s.w * ri);
            *reinterpret_cast<uint2*>(Ch + (size_t)r * 64 + col) = u;
        }
    }

    // ---- colsums: cs_j = sum_i E[i][j]*rinv[i]  (col pair 2t,2t+1) --------
    {
        const int jb_ = t >> 6;
        const int wn_ = (t >> 4) & 3;
        const int nf_ = (t >> 2) & 3;
        const int l2_ = t & 3;
        const char* base0 = smc + A_ESM + jb_ * 16384 + wn_ * 2048 + l2_ * 16 + nf_ * 4;
        float c0 = 0.f, c1 = 0.f;
        #pragma unroll
        for (int wm_ = 0; wm_ < 4; wm_++) {
            #pragma unroll
            for (int p = 0; p < 2; p++) {
                #pragma unroll
                for (int lr = 0; lr < 8; lr++) {
                    const int i = wm_ * 16 + p * 8 + lr;
                    uint32_t u = *reinterpret_cast<const uint32_t*>(
                        base0 + wm_ * 512 + p * 8192 + lr * 64);
                    float2 f = __half22float2(*reinterpret_cast<__half2*>(&u));
                    c0 += rs[i] * f.x;
                    c1 += rs[i] * f.y;
                }
            }
        }
        atomicAdd(&sums[g * 1024 + 2 * t + 0], c0);
        atomicAdd(&sums[g * 1024 + 2 * t + 1], c1);
    }
}

// ---------------------------------------------------------------------------
// Kernel 3: residual + LayerNorm (ctx read as fp16)
// ---------------------------------------------------------------------------
__global__ __launch_bounds__(256) void ln_kernel(
    const float* __restrict__ x,
    const float* __restrict__ gamma,
    const float* __restrict__ beta,
    float* __restrict__ out)
{
    const int row = blockIdx.x;
    const int t = threadIdx.x;
    const float* xr = x + (size_t)row * NTDIM;
    const __half* cr = g_ctx + (size_t)row * NTDIM;

    float h[4];
    float s = 0.0f, sq = 0.0f;
    #pragma unroll
    for (int i = 0; i < 4; i++) {
        int idx = t + i * 256;
        h[i] = xr[idx] + __half2float(cr[idx]);
        s  += h[i];
        sq += h[i] * h[i];
    }
    #pragma unroll
    for (int off = 16; off; off >>= 1) {
        s  += __shfl_xor_sync(0xffffffffu, s,  off);
        sq += __shfl_xor_sync(0xffffffffu, sq, off);
    }
    __shared__ float rsum[8], rsq[8];
    int warp = t >> 5, lane = t & 31;
    if (lane == 0) { rsum[warp] = s; rsq[warp] = sq; }
    __syncthreads();
    float S = 0.0f, SQ = 0.0f;
    #pragma unroll
    for (int w = 0; w < 8; w++) { S += rsum[w]; SQ += rsq[w]; }
    float mean = S * (1.0f / NTDIM);
    float var  = SQ * (1.0f / NTDIM) - mean * mean;
    float inv  = rsqrtf(var + LNEPS);
    float* orow = out + (size_t)row * NTDIM;
    #pragma unroll
    for (int i = 0; i < 4; i++) {
        int idx = t + i * 256;
        orow[idx] = (h[i] - mean) * inv * gamma[idx] + beta[idx];
    }
}

// ---------------------------------------------------------------------------
extern "C" void kernel_launch(void* const* d_in, const int* in_sizes, int n_in,
                              void* d_out, int out_size)
{
    const float* x     = (const float*)d_in[0];
    const float* Wq    = (const float*)d_in[1];
    const float* bq    = (const float*)d_in[2];
    const float* Wk    = (const float*)d_in[3];
    const float* bk    = (const float*)d_in[4];
    const float* Wv    = (const float*)d_in[5];
    const float* bv    = (const float*)d_in[6];
    const float* gamma = (const float*)d_in[7];
    const float* beta  = (const float*)d_in[8];

    float* out  = (float*)d_out;
    float* sums = out + (size_t)M_ROWS * NTDIM;

    cudaFuncSetAttribute(qkv_mma_kernel,
                         cudaFuncAttributeMaxDynamicSharedMemorySize, QKV_SMEM);
    cudaFuncSetAttribute(attn_mma_kernel,
                         cudaFuncAttributeMaxDynamicSharedMemorySize, A_SMEM);

    cvt_all_kernel<<<7168, 256>>>(x, Wq, Wk, Wv, sums);

    dim3 gq(4, 32, 3);
    qkv_mma_kernel<<<gq, 256, QKV_SMEM>>>(bq, bk, bv);

    dim3 ga(16, 64);
    attn_mma_kernel<<<ga, 512, A_SMEM>>>(sums);

    ln_kernel<<<M_ROWS, 256>>>(x, gamma, beta, out);
}

// round 17
// speedup vs baseline: 1.0438x; 1.0438x over previous
#include <cuda_runtime.h>
#include <cuda_fp16.h>
#include <cstdint>
#include <math.h>

// Problem constants
#define M_ROWS   4096      // B*S
#define NTDIM    1024
#define NGROUP   64        // B*heads
#define DPH      64
#define SEQ      1024
#define LNEPS    1e-5f
// softmax scale folded into Q:  q' = q * log2(e)/32;  E = 2^relu(q'.k)
#define QSCALE   0.04508422002777998f

// Scratch (allocation-free rule: __device__ globals), all fp16
__device__ __half g_q[M_ROWS * NTDIM];
__device__ __half g_k[M_ROWS * NTDIM];
__device__ __half g_v[M_ROWS * NTDIM];
__device__ __half g_ctx[M_ROWS * NTDIM];
__device__ __half g_x[M_ROWS * NTDIM];
__device__ __half g_w[3 * NTDIM * NTDIM];

// ===========================================================================
// PTX helpers: mma.sync (HMMA f16) + ldmatrix + cp.async
// ===========================================================================
__device__ __forceinline__ uint32_t smem_u32(const void* p) {
    uint32_t a;
    asm("{ .reg .u64 t; cvta.to.shared.u64 t, %1; cvt.u32.u64 %0, t; }" : "=r"(a) : "l"(p));
    return a;
}
__device__ __forceinline__ void ldsm_x4(uint32_t* r, uint32_t addr) {
    asm volatile("ldmatrix.sync.aligned.m8n8.x4.shared.b16 {%0,%1,%2,%3}, [%4];"
                 : "=r"(r[0]), "=r"(r[1]), "=r"(r[2]), "=r"(r[3]) : "r"(addr));
}
__device__ __forceinline__ void ldsm_x4_t(uint32_t* r, uint32_t addr) {
    asm volatile("ldmatrix.sync.aligned.m8n8.x4.trans.shared.b16 {%0,%1,%2,%3}, [%4];"
                 : "=r"(r[0]), "=r"(r[1]), "=r"(r[2]), "=r"(r[3]) : "r"(addr));
}
__device__ __forceinline__ void mma_f16(float* d, const uint32_t* a,
                                        uint32_t b0, uint32_t b1) {
    asm volatile(
        "mma.sync.aligned.m16n8k16.row.col.f32.f16.f16.f32 "
        "{%0,%1,%2,%3}, {%4,%5,%6,%7}, {%8,%9}, {%0,%1,%2,%3};"
        : "+f"(d[0]), "+f"(d[1]), "+f"(d[2]), "+f"(d[3])
        : "r"(a[0]), "r"(a[1]), "r"(a[2]), "r"(a[3]), "r"(b0), "r"(b1));
}
__device__ __forceinline__ void cpa16(uint32_t dst, const void* src) {
    size_t gp;
    asm("cvta.to.global.u64 %0, %1;" : "=l"(gp) : "l"(src));
    asm volatile("cp.async.cg.shared.global [%0], [%1], 16;" :: "r"(dst), "l"(gp) : "memory");
}
__device__ __forceinline__ void cpa_commit() {
    asm volatile("cp.async.commit_group;" ::: "memory");
}
__device__ __forceinline__ void cpa_wait0() {
    asm volatile("cp.async.wait_group 0;" ::: "memory");
}
__device__ __forceinline__ void cpa_wait1() {
    asm volatile("cp.async.wait_group 1;" ::: "memory");
}
__device__ __forceinline__ uint32_t pack_h2(float lo, float hi) {
    __half2 v = __floats2half2_rn(lo, hi);
    return *reinterpret_cast<uint32_t*>(&v);
}
// bare MUFU exp2 (relu'd input is in [0, ~8])
__device__ __forceinline__ float ex2(float x) {
    float r;
    asm("ex2.approx.f32 %0, %1;" : "=f"(r) : "f"(x));
    return r;
}

// ---------------------------------------------------------------------------
// Kernel 0: fp32 -> fp16 for x + Wq + Wk + Wv; blocks < 256 also zero sums.
// ---------------------------------------------------------------------------
__global__ __launch_bounds__(256) void cvt_all_kernel(
    const float* __restrict__ x, const float* __restrict__ wq,
    const float* __restrict__ wk, const float* __restrict__ wv,
    float* __restrict__ sums)
{
    const int b = blockIdx.x;
    const float* src; __half* dst;
    if (b < 4096)      { src = x  + (size_t)b * 1024;          dst = g_x + (size_t)b * 1024; }
    else if (b < 5120) { src = wq + (size_t)(b - 4096) * 1024; dst = g_w + (size_t)(b - 4096) * 1024; }
    else if (b < 6144) { src = wk + (size_t)(b - 5120) * 1024; dst = g_w + 1048576 + (size_t)(b - 5120) * 1024; }
    else               { src = wv + (size_t)(b - 6144) * 1024; dst = g_w + 2097152 + (size_t)(b - 6144) * 1024; }
    const int i = threadIdx.x * 4;
    float4 v = *reinterpret_cast<const float4*>(src + i);
    uint2 u;
    u.x = pack_h2(v.x, v.y);
    u.y = pack_h2(v.z, v.w);
    *reinterpret_cast<uint2*>(dst + i) = u;
    if (b < 256) sums[b * 256 + threadIdx.x] = 0.0f;
}

// ---------------------------------------------------------------------------
// Kernel 1: QKV projection via mma.sync f16, fp32 accum, 3-stage cp.async.
// C = X @ W^T + b -> fp16.  CTA tile 128x128, k-stage 64.  2 CTAs/SM.
// Q output is pre-scaled by QSCALE (softmax scale folded in).
// ---------------------------------------------------------------------------
#define QST_AH 0
#define QST_BH 16384
#define QST_SZ 32768
#define QKV_SMEM (3 * QST_SZ)

__global__ __launch_bounds__(256, 2) void qkv_mma_kernel(
    const float* __restrict__ bq, const float* __restrict__ bk, const float* __restrict__ bv)
{
    extern __shared__ char smc[];
    const uint32_t smb = smem_u32(smc);
    const int t = threadIdx.x;
    const int w = t >> 5;
    const int l = t & 31;
    const int z = blockIdx.z;
    const __half* __restrict__ Wh = g_w + (size_t)z * NTDIM * NTDIM;
    const float* bias = (z == 0) ? bq : (z == 1) ? bk : bv;
    __half* outh = (z == 0) ? g_q : (z == 1) ? g_k : g_v;
    const float osc = (z == 0) ? QSCALE : 1.0f;
    const int m0 = blockIdx.y * 128;
    const int n0 = blockIdx.x * 128;
    const int wr0 = (w >> 1) * 32;
    const int wn0 = (w & 1) * 64;

    const int sr[4] = { (t + 0) >> 3, (t + 256) >> 3, (t + 512) >> 3, (t + 768) >> 3 };
    const int sc = t & 7;

    float acc[2][8][4];
    #pragma unroll
    for (int a = 0; a < 2; a++)
        #pragma unroll
        for (int b = 0; b < 8; b++)
            #pragma unroll
            for (int c = 0; c < 4; c++) acc[a][b][c] = 0.0f;

    auto issue_stage = [&](int s, int buf) {
        const int k0 = s * 64;
        const uint32_t sb = smb + buf * QST_SZ;
        #pragma unroll
        for (int i = 0; i < 4; i++) {
            const int r = sr[i];
            const uint32_t doff = r * 128 + (((sc ^ (r & 7)) << 4));
            cpa16(sb + QST_AH + doff, g_x + (size_t)(m0 + r) * NTDIM + k0 + sc * 8);
            cpa16(sb + QST_BH + doff, Wh + (size_t)(n0 + r) * NTDIM + k0 + sc * 8);
        }
        cpa_commit();
    };

    issue_stage(0, 0);
    issue_stage(1, 1);

    for (int s = 0; s < 16; s++) {
        if (s == 15) cpa_wait0(); else cpa_wait1();
        __syncthreads();
        if (s < 14) issue_stage(s + 2, (s + 2) % 3);
        const uint32_t bb = smb + (s % 3) * QST_SZ;

        #pragma unroll
        for (int kt = 0; kt < 4; kt++) {
            const int chunk = kt * 2 + (l >> 4);
            uint32_t ah[2][4];
            #pragma unroll
            for (int mf = 0; mf < 2; mf++) {
                const int r = wr0 + mf * 16 + (l & 15);
                ldsm_x4(ah[mf], bb + QST_AH + r * 128 + (((chunk ^ (r & 7)) << 4)));
            }
            #pragma unroll
            for (int nq = 0; nq < 4; nq++) {
                const int rr = wn0 + nq * 16 + (l & 15);
                uint32_t bh[4];
                ldsm_x4(bh, bb + QST_BH + rr * 128 + (((chunk ^ (rr & 7)) << 4)));
                #pragma unroll
                for (int mf = 0; mf < 2; mf++) {
                    #pragma unroll
                    for (int nh = 0; nh < 2; nh++)
                        mma_f16(acc[mf][nq * 2 + nh], ah[mf], bh[nh], bh[2 + nh]);
                }
            }
        }
    }

    // epilogue: (acc + bias) * osc -> fp16
    const int lr = l >> 2;
    const int lc = (l & 3) * 2;
    #pragma unroll
    for (int mf = 0; mf < 2; mf++) {
        #pragma unroll
        for (int nf = 0; nf < 8; nf++) {
            const int col = n0 + wn0 + nf * 8 + lc;
            const int row = m0 + wr0 + mf * 16 + lr;
            const float* d = acc[mf][nf];
            *reinterpret_cast<uint32_t*>(outh + (size_t)row * NTDIM + col) =
                pack_h2((d[0] + bias[col]) * osc, (d[1] + bias[col + 1]) * osc);
            *reinterpret_cast<uint32_t*>(outh + (size_t)(row + 8) * NTDIM + col) =
                pack_h2((d[2] + bias[col]) * osc, (d[3] + bias[col + 1]) * osc);
        }
    }
}

// ---------------------------------------------------------------------------
// Kernel 2: attention, single fused pass, 512 threads (16 warps).
// CTA = 64 query rows x one head-group.  Warp = 16 rows x 32-key slice.
// E = 2^relu(q'.k) via bare ex2 (scale pre-folded into q').
// E stored thread-linear in smem; rowsum reduction deferred; ctx out fp16.
// ---------------------------------------------------------------------------
#define A_ESM   0           // 8 jb x 16KB = 131072 (thread-linear layout)
#define A_QH    131072      // 8192
#define A_KV    139264      // 2 x (K 16384 + V 16384) = 65536 (loop only)
#define A_RED   139264      // 4 x 17408 = 69632 (epilogue, reuses KV)
#define A_RS    208896      // 64 floats
#define A_SMEM  209152

__global__ __launch_bounds__(512) void attn_mma_kernel(float* __restrict__ sums)
{
    extern __shared__ char smc[];
    const uint32_t smb = smem_u32(smc);
    float* rs = reinterpret_cast<float*>(smc + A_RS);

    const int ib = blockIdx.x;   // 0..15 (64-row block)
    const int g  = blockIdx.y;   // 0..63
    const int t  = threadIdx.x;
    const int w  = t >> 5;
    const int l  = t & 31;
    const int wm = w & 3;        // 4 row groups of 16
    const int wn = w >> 2;       // 4 key-slice groups of 32

    const __half* __restrict__ qhp = g_q + (size_t)g * 65536 + ib * 4096;
    const __half* __restrict__ khp = g_k + (size_t)g * 65536;
    const __half* __restrict__ vhp = g_v + (size_t)g * 65536;

    if (t < 64) rs[t] = 0.0f;

    // stage Q: 512 chunk-tasks, 1 per thread
    {
        int row = t >> 3, ch = t & 7;
        cpa16(smb + A_QH + row * 128 + ((ch ^ (row & 7)) << 4), qhp + row * 64 + ch * 8);
    }
    auto stage_kv = [&](int jb, int buf) {
        const uint32_t dst = smb + A_KV + buf * 32768;
        #pragma unroll
        for (int i = 0; i < 2; i++) {
            int id = t + i * 512;
            int row = id >> 3, ch = id & 7;
            uint32_t doff = row * 128 + ((ch ^ (row & 7)) << 4);
            cpa16(dst + doff, khp + (size_t)(jb * 128 + row) * 64 + ch * 8);
            cpa16(dst + 16384 + doff, vhp + (size_t)(jb * 128 + row) * 64 + ch * 8);
        }
        cpa_commit();
    };
    stage_kv(0, 0);

    float ev[8][4];
    #pragma unroll
    for (int b = 0; b < 8; b++)
        #pragma unroll
        for (int c = 0; c < 4; c++) ev[b][c] = 0.0f;

    uint32_t qf[4][4];            // hoisted Q fragments (loaded at jb==0)
    float sAcc0 = 0.0f, sAcc1 = 0.0f;   // deferred rowsum partials
    char* const epp = smc + A_ESM + t * 16;  // thread-linear E base

    for (int jb = 0; jb < 8; jb++) {
        cpa_wait0();
        __syncthreads();
        if (jb < 7) stage_kv(jb + 1, (jb + 1) & 1);
        const uint32_t kb = smb + A_KV + (jb & 1) * 32768;
        const uint32_t vb = kb + 16384;

        if (jb == 0) {
            #pragma unroll
            for (int kc = 0; kc < 4; kc++) {
                const int chunk = kc * 2 + (l >> 4);
                const int r = wm * 16 + (l & 15);
                ldsm_x4(qf[kc], smb + A_QH + r * 128 + ((chunk ^ (r & 7)) << 4));
            }
        }

        // ---- QK^T: warp owns rows wm*16.., cols wn*32.. -------------------
        float acc[4][4];
        #pragma unroll
        for (int b = 0; b < 4; b++)
            #pragma unroll
            for (int c = 0; c < 4; c++) acc[b][c] = 0.0f;

        #pragma unroll
        for (int kc = 0; kc < 4; kc++) {
            const int chunk = kc * 2 + (l >> 4);
            #pragma unroll
            for (int nfp = 0; nfp < 2; nfp++) {
                const int rr = wn * 32 + nfp * 16 + (l & 15);
                uint32_t bh[4];
                ldsm_x4(bh, kb + rr * 128 + ((chunk ^ (rr & 7)) << 4));
                #pragma unroll
                for (int nh = 0; nh < 2; nh++)
                    mma_f16(acc[nfp * 2 + nh], qf[kc], bh[nh], bh[2 + nh]);
            }
        }

        // ---- E = 2^relu(z'); E -> smem (2 x STS.128); reg rowsums ---------
        uint32_t pk[4][2];
        #pragma unroll
        for (int nf = 0; nf < 4; nf++) {
            float* d = acc[nf];
            float e0 = ex2(fmaxf(d[0], 0.0f));
            float e1 = ex2(fmaxf(d[1], 0.0f));
            float e2 = ex2(fmaxf(d[2], 0.0f));
            float e3 = ex2(fmaxf(d[3], 0.0f));
            sAcc0 += e0 + e1;
            sAcc1 += e2 + e3;
            pk[nf][0] = pack_h2(e0, e1);
            pk[nf][1] = pack_h2(e2, e3);
        }
        {
            uint4 u0 = make_uint4(pk[0][0], pk[1][0], pk[2][0], pk[3][0]);
            uint4 u1 = make_uint4(pk[0][1], pk[1][1], pk[2][1], pk[3][1]);
            *reinterpret_cast<uint4*>(epp + (jb << 14)) = u0;
            *reinterpret_cast<uint4*>(epp + (jb << 14) + 8192) = u1;
        }

        // ---- EV += E @ V over this warp's 32-key slice (2 k16 chunks) -----
        #pragma unroll
        for (int c = 0; c < 2; c++) {
            const int krow = wn * 32 + c * 16 + (l & 7) + (((l >> 3) & 1) << 3);
            uint32_t A[4] = { pk[2 * c][0], pk[2 * c][1],
                              pk[2 * c + 1][0], pk[2 * c + 1][1] };
            #pragma unroll
            for (int nt = 0; nt < 4; nt++) {
                const int nch = nt * 2 + (l >> 4);
                uint32_t vh4[4];
                ldsm_x4_t(vh4, vb + krow * 128 + ((nch ^ (krow & 7)) << 4));
                mma_f16(ev[2 * nt], A, vh4[0], vh4[1]);
                mma_f16(ev[2 * nt + 1], A, vh4[2], vh4[3]);
            }
        }
    }

    // deferred rowsum reduction: one shuffle-pass + one atomic pair
    {
        sAcc0 += __shfl_xor_sync(0xffffffffu, sAcc0, 1);
        sAcc0 += __shfl_xor_sync(0xffffffffu, sAcc0, 2);
        sAcc1 += __shfl_xor_sync(0xffffffffu, sAcc1, 1);
        sAcc1 += __shfl_xor_sync(0xffffffffu, sAcc1, 2);
        const int rbase = wm * 16 + (l >> 2);
        if ((l & 3) == 0) {
            atomicAdd(&rs[rbase], sAcc0);
            atomicAdd(&rs[rbase + 8], sAcc1);
        }
    }
    __syncthreads();   // rowsums complete; E smem stable; KV buffers free

    if (t < 64) rs[t] = 1.0f / rs[t];

    // ---- cross-warp EV reduce: write partials (row stride 272B, per wn) ---
    {
        char* red = smc + A_RED + wn * 17408;
        const int row = wm * 16 + (l >> 2);
        #pragma unroll
        for (int nf = 0; nf < 8; nf++) {
            const int col = nf * 8 + 2 * (l & 3);
            *reinterpret_cast<float2*>(red + row * 272 + col * 4) =
                make_float2(ev[nf][0], ev[nf][1]);
            *reinterpret_cast<float2*>(red + (row + 8) * 272 + col * 4) =
                make_float2(ev[nf][2], ev[nf][3]);
        }
    }
    __syncthreads();

    // ---- reduce 4 partials, scale by rinv, write ctx (fp16) ---------------
    {
        const int r = t >> 3;               // 0..63
        const float ri = rs[r];
        __half* __restrict__ Ch = g_ctx + (size_t)g * 65536 + ib * 4096;
        #pragma unroll
        for (int it = 0; it < 2; it++) {
            const int col = ((t & 7) * 2 + it) * 4;   // 0..60
            float4 s = make_float4(0.f, 0.f, 0.f, 0.f);
            #pragma unroll
            for (int p = 0; p < 4; p++) {
                float4 v = *reinterpret_cast<const float4*>(
                    smc + A_RED + p * 17408 + r * 272 + col * 4);
                s.x += v.x; s.y += v.y; s.z += v.z; s.w += v.w;
            }
            uint2 u;
            u.x = pack_h2(s.x * ri, s.y * ri);
            u.y = pack_h2(s.z * ri, s.w * ri);
            *reinterpret_cast<uint2*>(Ch + (size_t)r * 64 + col) = u;
        }
    }

    // ---- colsums: cs_j = sum_i E[i][j]*rinv[i]  (col pair 2t,2t+1) --------
    {
        const int jb_ = t >> 6;
        const int wn_ = (t >> 4) & 3;
        const int nf_ = (t >> 2) & 3;
        const int l2_ = t & 3;
        const char* base0 = smc + A_ESM + jb_ * 16384 + wn_ * 2048 + l2_ * 16 + nf_ * 4;
        float c0 = 0.f, c1 = 0.f;
        #pragma unroll
        for (int wm_ = 0; wm_ < 4; wm_++) {
            #pragma unroll
            for (int p = 0; p < 2; p++) {
                #pragma unroll
                for (int lr = 0; lr < 8; lr++) {
                    const int i = wm_ * 16 + p * 8 + lr;
                    uint32_t u = *reinterpret_cast<const uint32_t*>(
                        base0 + wm_ * 512 + p * 8192 + lr * 64);
                    float2 f = __half22float2(*reinterpret_cast<__half2*>(&u));
                    c0 += rs[i] * f.x;
                    c1 += rs[i] * f.y;
                }
            }
        }
        atomicAdd(&sums[g * 1024 + 2 * t + 0], c0);
        atomicAdd(&sums[g * 1024 + 2 * t + 1], c1);
    }
}

// ---------------------------------------------------------------------------
// Kernel 3: residual + LayerNorm (vectorized: float4 x, uint2 ctx, float4 out)
// ---------------------------------------------------------------------------
__global__ __launch_bounds__(256) void ln_kernel(
    const float* __restrict__ x,
    const float* __restrict__ gamma,
    const float* __restrict__ beta,
    float* __restrict__ out)
{
    const int row = blockIdx.x;
    const int t = threadIdx.x;
    const float* xr = x + (size_t)row * NTDIM;
    const __half* cr = g_ctx + (size_t)row * NTDIM;
    const int base = t * 4;

    float4 xv = *reinterpret_cast<const float4*>(xr + base);
    uint2 cu = *reinterpret_cast<const uint2*>(cr + base);
    float2 c01 = __half22float2(*reinterpret_cast<__half2*>(&cu.x));
    float2 c23 = __half22float2(*reinterpret_cast<__half2*>(&cu.y));

    float h[4];
    h[0] = xv.x + c01.x;
    h[1] = xv.y + c01.y;
    h[2] = xv.z + c23.x;
    h[3] = xv.w + c23.y;
    float s  = h[0] + h[1] + h[2] + h[3];
    float sq = h[0]*h[0] + h[1]*h[1] + h[2]*h[2] + h[3]*h[3];

    #pragma unroll
    for (int off = 16; off; off >>= 1) {
        s  += __shfl_xor_sync(0xffffffffu, s,  off);
        sq += __shfl_xor_sync(0xffffffffu, sq, off);
    }
    __shared__ float rsum[8], rsq[8];
    int warp = t >> 5, lane = t & 31;
    if (lane == 0) { rsum[warp] = s; rsq[warp] = sq; }
    __syncthreads();
    float S = 0.0f, SQ = 0.0f;
    #pragma unroll
    for (int w = 0; w < 8; w++) { S += rsum[w]; SQ += rsq[w]; }
    float mean = S * (1.0f / NTDIM);
    float var  = SQ * (1.0f / NTDIM) - mean * mean;
    float inv  = rsqrtf(var + LNEPS);

    float4 gv = *reinterpret_cast<const float4*>(gamma + base);
    float4 bv = *reinterpret_cast<const float4*>(beta + base);
    float4 o;
    o.x = (h[0] - mean) * inv * gv.x + bv.x;
    o.y = (h[1] - mean) * inv * gv.y + bv.y;
    o.z = (h[2] - mean) * inv * gv.z + bv.z;
    o.w = (h[3] - mean) * inv * gv.w + bv.w;
    *reinterpret_cast<float4*>(out + (size_t)row * NTDIM + base) = o;
}

// ---------------------------------------------------------------------------
extern "C" void kernel_launch(void* const* d_in, const int* in_sizes, int n_in,
                              void* d_out, int out_size)
{
    const float* x     = (const float*)d_in[0];
    const float* Wq    = (const float*)d_in[1];
    const float* bq    = (const float*)d_in[2];
    const float* Wk    = (const float*)d_in[3];
    const float* bk    = (const float*)d_in[4];
    const float* Wv    = (const float*)d_in[5];
    const float* bv    = (const float*)d_in[6];
    const float* gamma = (const float*)d_in[7];
    const float* beta  = (const float*)d_in[8];

    float* out  = (float*)d_out;
    float* sums = out + (size_t)M_ROWS * NTDIM;

    cudaFuncSetAttribute(qkv_mma_kernel,
                         cudaFuncAttributeMaxDynamicSharedMemorySize, QKV_SMEM);
    cudaFuncSetAttribute(attn_mma_kernel,
                         cudaFuncAttributeMaxDynamicSharedMemorySize, A_SMEM);

    cvt_all_kernel<<<7168, 256>>>(x, Wq, Wk, Wv, sums);

    dim3 gq(8, 32, 3);
    qkv_mma_kernel<<<gq, 256, QKV_SMEM>>>(bq, bk, bv);

    dim3 ga(16, 64);
    attn_mma_kernel<<<ga, 512, A_SMEM>>>(sums);

    ln_kernel<<<M_ROWS, 256>>>(x, gamma, beta, out);
}